// round 17
// baseline (speedup 1.0000x reference)
#include <cuda_runtime.h>
#include <cuda_fp16.h>
#include <cstdint>

// AttentionOutput: causal complex leaky-relu attention + linear head.
// B=4, N=4096, F=64.  fp16 mma.sync.m16n8k16, 32-row Q tiles, pipelined,
// 2 CTAs/SM (72KB smem, 128 regs). 256 equal-work pair-balanced CTAs.

#define NT 256
#define S2 36            // words (uint32) per 64-half row
// word offsets (single K/W buffers, double V)
#define QR2 0            // 32 x 36
#define QI2 1152
#define KR2 2304         // 64 x 36
#define KI2 4608
#define VB0 6912         // V buffer 0: VR +0, VI +2304
#define VB1 11520        // V buffer 1
#define WR2 16128        // 32 x 36
#define WI2 17280
#define SMH2 18432
#define SMB (SMH2 * 4)   // 73728 bytes -> 2 CTAs/SM
// float-unit aliases for the linear head (Q/K regions dead by then)
#define OFR 0            // 32 x 68
#define OFI 2176
#define WATTF 4352       // 64 x 68
#define BIASF 8704

__device__ __forceinline__ uint32_t pkh2(float lo, float hi) {
    __half2 h = __floats2half2_rn(lo, hi);
    return *(uint32_t*)&h;
}
__device__ __forceinline__ float rna(float x) {
    uint32_t u;
    asm("cvt.rna.tf32.f32 %0, %1;" : "=r"(u) : "f"(x));
    return __uint_as_float(u);
}

__device__ __forceinline__ void mma16(float* c, uint32_t a0, uint32_t a1,
                                      uint32_t a2, uint32_t a3,
                                      uint32_t b0, uint32_t b1) {
    asm volatile("mma.sync.aligned.m16n8k16.row.col.f32.f16.f16.f32 "
                 "{%0,%1,%2,%3},{%4,%5,%6,%7},{%8,%9},{%0,%1,%2,%3};"
                 : "+f"(c[0]), "+f"(c[1]), "+f"(c[2]), "+f"(c[3])
                 : "r"(a0), "r"(a1), "r"(a2), "r"(a3), "r"(b0), "r"(b1));
}
__device__ __forceinline__ void mma8(float* c, float a0, float a1, float a2, float a3,
                                     float b0, float b1) {
    uint32_t A0 = __float_as_uint(a0), A1 = __float_as_uint(a1);
    uint32_t A2 = __float_as_uint(a2), A3 = __float_as_uint(a3);
    uint32_t B0 = __float_as_uint(b0), B1 = __float_as_uint(b1);
    asm volatile("mma.sync.aligned.m16n8k8.row.col.f32.tf32.tf32.f32 "
                 "{%0,%1,%2,%3},{%4,%5,%6,%7},{%8,%9},{%0,%1,%2,%3};"
                 : "+f"(c[0]), "+f"(c[1]), "+f"(c[2]), "+f"(c[3])
                 : "r"(A0), "r"(A1), "r"(A2), "r"(A3), "r"(B0), "r"(B1));
}

#define SPLIT4(x0, x1, x2, x3, h0, h1, h2, h3, l0, l1, l2, l3)              \
    float h0 = rna(x0), h1 = rna(x1), h2 = rna(x2), h3 = rna(x3);           \
    float l0 = x0 - h0, l1 = x1 - h1, l2 = x2 - h2, l3 = x3 - h3;

// phase 1 + epilogue: scores for 32x64 tile, write W (single buffer)
__device__ __forceinline__ void phase1_epi(uint32_t* smh, int kt, int qi0,
                                           int i0w, int j0w, int g, int t, float scale)
{
    float crr[2][4], cii[2][4], csi[2][4];
    #pragma unroll
    for (int nb = 0; nb < 2; ++nb)
        #pragma unroll
        for (int r = 0; r < 4; ++r) { crr[nb][r] = 0.f; cii[nb][r] = 0.f; csi[nb][r] = 0.f; }

    #pragma unroll
    for (int kk = 0; kk < 4; ++kk) {
        const int k0 = kk * 8;
        const int qa = QR2 + (i0w + g) * S2 + k0 + t;
        uint32_t qr0 = smh[qa],            qr1 = smh[qa + 8 * S2];
        uint32_t qr2 = smh[qa + 4],        qr3 = smh[qa + 8 * S2 + 4];
        const int qb = qa + (QI2 - QR2);
        uint32_t qi0_ = smh[qb],           qi1 = smh[qb + 8 * S2];
        uint32_t qi2 = smh[qb + 4],        qi3 = smh[qb + 8 * S2 + 4];
        #pragma unroll
        for (int nb = 0; nb < 2; ++nb) {
            const int kb = KR2 + (j0w + nb * 8 + g) * S2 + k0 + t;
            uint32_t kr0 = smh[kb],        kr1 = smh[kb + 4];
            uint32_t ki0 = smh[kb + 2304], ki1 = smh[kb + 2304 + 4];
            mma16(crr[nb], qr0, qr1, qr2, qr3, kr0, kr1);
            mma16(cii[nb], qi0_, qi1, qi2, qi3, ki0, ki1);
            mma16(csi[nb], qr0, qr1, qr2, qr3, ki0, ki1);
            mma16(csi[nb], qi0_, qi1, qi2, qi3, kr0, kr1);
        }
    }

    #pragma unroll
    for (int nb = 0; nb < 2; ++nb) {
        float vr_[4], vi_[4];
        #pragma unroll
        for (int r = 0; r < 4; ++r) {
            int il = i0w + g + ((r & 2) ? 8 : 0);
            int jg = kt + j0w + nb * 8 + 2 * t + (r & 1);
            float sr = (crr[nb][r] - cii[nb][r]) * scale;
            float si = csi[nb][r] * scale;
            sr = sr >= 0.f ? sr : 0.01f * sr;
            si = si >= 0.f ? si : 0.01f * si;
            if (jg > qi0 + il) { sr = 0.f; si = 0.f; }
            vr_[r] = sr; vi_[r] = si;
        }
        const int wb = WR2 + (i0w + g) * S2 + (j0w >> 1) + nb * 4 + t;
        smh[wb]                 = pkh2(vr_[0], vr_[1]);
        smh[wb + 8 * S2]        = pkh2(vr_[2], vr_[3]);
        smh[wb + 1152]          = pkh2(vi_[0], vi_[1]);
        smh[wb + 1152 + 8 * S2] = pkh2(vi_[2], vi_[3]);
    }
}

__device__ __forceinline__ void phase2f(uint32_t* smh, int vbase, int i0p, int f0p,
                                        int g, int t, float o_r[2][4], float o_i[2][4])
{
    #pragma unroll
    for (int kk = 0; kk < 4; ++kk) {
        const int k0 = kk * 8;
        const int wa = WR2 + (i0p + g) * S2 + k0 + t;
        uint32_t wr0 = smh[wa],            wr1 = smh[wa + 8 * S2];
        uint32_t wr2 = smh[wa + 4],        wr3 = smh[wa + 8 * S2 + 4];
        uint32_t wi0 = smh[wa + 1152],     wi1 = smh[wa + 1152 + 8 * S2];
        uint32_t wi2 = smh[wa + 1152 + 4], wi3 = smh[wa + 1152 + 8 * S2 + 4];
        #pragma unroll
        for (int nb = 0; nb < 2; ++nb) {
            const int f = f0p + nb * 8 + g;
            const int xm = (f >> 3) & 3;
            const int vb = vbase + f * S2 + k0 + (t ^ xm);
            uint32_t v0 = smh[vb],        v1 = smh[vb + 4];
            uint32_t u0 = smh[vb + 2304], u1 = smh[vb + 2304 + 4];
            mma16(o_r[nb], wr0, wr1, wr2, wr3, v0, v1);
            mma16(o_i[nb], wi0, wi1, wi2, wi3, u0, u1);
        }
    }
}

__global__ __launch_bounds__(NT, 2)
void attn_k(const float2* __restrict__ Qg, const float2* __restrict__ Kg,
            const float2* __restrict__ Vg, const float* __restrict__ Wg,
            const float* __restrict__ bg, float2* __restrict__ Og)
{
    extern __shared__ uint32_t smh[];
    float* smf = (float*)smh;
    const int tid = threadIdx.x, w = tid >> 5, l = tid & 31;
    const int g = l >> 2, t = l & 3;
    const int b = blockIdx.y;
    const int N = 4096;

    const int i0w = (w >> 2) * 16, j0w = (w & 3) * 16;     // phase-1: 16x16 warp tile
    const int i0p = (w & 1) * 16, f0p = (w >> 1) * 16;     // phase-2: 16x16 warp tile
    const float scale = 1.0f / 64.0f;                      // 1/sqrt(4096)

    // complementary pair of 32-row qtiles: nkt(m) = (m>>1)+1; pair sum = 65 for all
    #pragma unroll 1
    for (int pi = 0; pi < 2; ++pi) {
        const int mq = pi ? (127 - (int)blockIdx.x) : (int)blockIdx.x;
        const int qi0 = mq * 32;
        const int nkt = (mq >> 1) + 1;

        __syncthreads();   // previous iteration's smem reads complete

        // ---- prologue: load Q (32x64) and KV[0] (V -> buffer 0) ----
        {
            const float4* Qp4 = (const float4*)(Qg + ((size_t)b * N + qi0) * 64);
            for (int idx = tid; idx < 1024; idx += NT) {
                float4 q = Qp4[idx];
                int j = idx >> 5, fp = idx & 31;
                smh[QR2 + j * S2 + fp] = pkh2(q.x, q.z);
                smh[QI2 + j * S2 + fp] = pkh2(q.y, q.w);
            }
            const float4* Kp4 = (const float4*)(Kg + ((size_t)b * N) * 64);
            const float2* Vp  = Vg + ((size_t)b * N) * 64;
            for (int idx = tid; idx < 2048; idx += NT) {
                float4 kv = Kp4[idx];
                int j = idx >> 5, fp = idx & 31;
                smh[KR2 + j * S2 + fp] = pkh2(kv.x, kv.z);
                smh[KI2 + j * S2 + fp] = pkh2(kv.y, kv.w);
                int jp = idx >> 6, f = idx & 63;
                float2 v0 = Vp[(2 * jp) * 64 + f];
                float2 v1 = Vp[(2 * jp + 1) * 64 + f];
                int js = jp ^ ((f >> 3) & 3);
                smh[VB0 + f * S2 + js]        = pkh2(v0.x, v1.x);
                smh[VB0 + 2304 + f * S2 + js] = pkh2(v0.y, v1.y);
            }
        }

        float o_r[2][4], o_i[2][4];
        #pragma unroll
        for (int nb = 0; nb < 2; ++nb)
            #pragma unroll
            for (int r = 0; r < 4; ++r) { o_r[nb][r] = 0.f; o_i[nb][r] = 0.f; }

        __syncthreads();
        phase1_epi(smh, 0, qi0, i0w, j0w, g, t, scale);

        for (int tt = 0; tt < nkt; ++tt) {
            const int p = tt & 1;
            const int vb_cur = p ? VB1 : VB0;
            const int vb_nxt = p ? VB0 : VB1;
            const bool more = (tt + 1 < nkt);

            __syncthreads();   // W[tt] written; prior interval's smem reads done

            // ---- interval A: stage KV[tt+1] (packed), phase2(tt), STS ----
            uint32_t kw[16], vw[16];
            if (more) {
                const float4* Kp4 = (const float4*)(Kg + ((size_t)b * N + (tt + 1) * 64) * 64);
                const float2* Vp  = Vg + ((size_t)b * N + (tt + 1) * 64) * 64;
                #pragma unroll
                for (int u = 0; u < 8; ++u) {
                    int idx = tid + u * NT;
                    float4 kv = Kp4[idx];
                    kw[2 * u]     = pkh2(kv.x, kv.z);
                    kw[2 * u + 1] = pkh2(kv.y, kv.w);
                    int jp = idx >> 6, f = idx & 63;
                    float2 v0 = Vp[(2 * jp) * 64 + f];
                    float2 v1 = Vp[(2 * jp + 1) * 64 + f];
                    vw[2 * u]     = pkh2(v0.x, v1.x);
                    vw[2 * u + 1] = pkh2(v0.y, v1.y);
                }
            }

            phase2f(smh, vb_cur, i0p, f0p, g, t, o_r, o_i);

            if (more) {
                #pragma unroll
                for (int u = 0; u < 8; ++u) {
                    int idx = tid + u * NT;
                    int j = idx >> 5, fp = idx & 31;
                    smh[KR2 + j * S2 + fp] = kw[2 * u];      // K[tt] dead: safe
                    smh[KI2 + j * S2 + fp] = kw[2 * u + 1];
                    int jp = idx >> 6, f = idx & 63;
                    int js = jp ^ ((f >> 3) & 3);
                    smh[vb_nxt + f * S2 + js]        = vw[2 * u];
                    smh[vb_nxt + 2304 + f * S2 + js] = vw[2 * u + 1];
                }
            }

            __syncthreads();   // KV[tt+1] in smem; phase2(tt) reads done

            // ---- interval B: phase1(tt+1) + epilogue -> W ----
            if (more)
                phase1_epi(smh, (tt + 1) * 64, qi0, i0w, j0w, g, t, scale);
        }

        // ---- linear head via tf32 mma: out = O @ Watt^T + b ----
        __syncthreads();
        #pragma unroll
        for (int nb = 0; nb < 2; ++nb)
            #pragma unroll
            for (int r = 0; r < 4; ++r) {
                int il = i0p + g + ((r & 2) ? 8 : 0);
                int fo = f0p + nb * 8 + 2 * t + (r & 1);
                smf[OFR + il * 68 + fo] = o_r[nb][r];
                smf[OFI + il * 68 + fo] = o_i[nb][r];
            }
        for (int idx = tid; idx < 64 * 64; idx += NT)
            smf[WATTF + (idx >> 6) * 68 + (idx & 63)] = Wg[idx];
        if (tid < 64) smf[BIASF + tid] = bg[tid];
        __syncthreads();

        float hr[2][4], hi_[2][4];
        #pragma unroll
        for (int nb = 0; nb < 2; ++nb)
            #pragma unroll
            for (int r = 0; r < 4; ++r) { hr[nb][r] = 0.f; hi_[nb][r] = 0.f; }

        for (int kk = 0; kk < 8; ++kk) {
            const int k0 = kk * 8;
            const int ab = OFR + (i0p + g) * 68 + k0 + t;
            float pr0 = smf[ab],     pr1 = smf[ab + 8 * 68];
            float pr2 = smf[ab + 4], pr3 = smf[ab + 8 * 68 + 4];
            const int ai = OFI + (i0p + g) * 68 + k0 + t;
            float pi0 = smf[ai],     pi1 = smf[ai + 8 * 68];
            float pi2 = smf[ai + 4], pi3 = smf[ai + 8 * 68 + 4];
            SPLIT4(pr0, pr1, pr2, pr3, orh0, orh1, orh2, orh3, orl0, orl1, orl2, orl3)
            SPLIT4(pi0, pi1, pi2, pi3, oih0, oih1, oih2, oih3, oil0, oil1, oil2, oil3)
            #pragma unroll
            for (int nb = 0; nb < 2; ++nb) {
                const int wb2 = WATTF + (f0p + nb * 8 + g) * 68 + k0 + t;
                float w0 = smf[wb2], w1 = smf[wb2 + 4];
                float wh0 = rna(w0), wl0 = w0 - wh0;
                float wh1 = rna(w1), wl1 = w1 - wh1;
                mma8(hr[nb], orh0, orh1, orh2, orh3, wh0, wh1);
                mma8(hr[nb], orl0, orl1, orl2, orl3, wh0, wh1);
                mma8(hr[nb], orh0, orh1, orh2, orh3, wl0, wl1);
                mma8(hi_[nb], oih0, oih1, oih2, oih3, wh0, wh1);
                mma8(hi_[nb], oil0, oil1, oil2, oil3, wh0, wh1);
                mma8(hi_[nb], oih0, oih1, oih2, oih3, wl0, wl1);
            }
        }

        float2* Ob = Og + ((size_t)b * N + qi0) * 64;
        #pragma unroll
        for (int nb = 0; nb < 2; ++nb)
            #pragma unroll
            for (int r = 0; r < 4; ++r) {
                int il = i0p + g + ((r & 2) ? 8 : 0);
                int fo = f0p + nb * 8 + 2 * t + (r & 1);
                float bb = smf[BIASF + fo];
                Ob[il * 64 + fo] = make_float2(hr[nb][r] + bb, hi_[nb][r] + bb);
            }
    }
}

extern "C" void kernel_launch(void* const* d_in, const int* in_sizes, int n_in,
                              void* d_out, int out_size)
{
    const float2* Q = (const float2*)d_in[0];
    const float2* K = (const float2*)d_in[1];
    const float2* V = (const float2*)d_in[2];
    const float*  W = (const float*)d_in[3];
    const float*  bb = (const float*)d_in[4];
    float2* O = (float2*)d_out;

    static bool attr_set = false;
    if (!attr_set) {
        cudaFuncSetAttribute(attn_k, cudaFuncAttributeMaxDynamicSharedMemorySize, SMB);
        attr_set = true;
    }

    attn_k<<<dim3(64, 4), NT, SMB>>>(Q, K, V, W, bb, O);
}